// round 2
// baseline (speedup 1.0000x reference)
#include <cuda_runtime.h>
#include <math.h>

// MemoryUnit: recurrent slot memory. One CTA per batch element (B=64 CTAs),
// state (M, pers) lives in shared memory across all S=2048 steps.
// Round 1: fp32 FFMA baseline, exact math to anchor correctness.

namespace {
constexpr int S_ = 2048;
constexpr int B_ = 64;
constexpr int D_ = 256;
constexpr int K_ = 16;
constexpr int NT = 256;
constexpr float EPSLN = 1e-5f;
constexpr float MOMC  = 0.9f;

__device__ __forceinline__ float geluf(float v) {
    return 0.5f * v * (1.0f + erff(v * 0.70710678118654752440f));
}
__device__ __forceinline__ float sigmf(float v) {
    return 1.0f / (1.0f + expf(-v));
}

// All 256 threads participate. Returns (sum a, sum b) to every thread.
__device__ __forceinline__ float2 block_reduce_2(float a, float b,
                                                 float* scratch, int lane, int wid) {
    #pragma unroll
    for (int off = 16; off; off >>= 1) {
        a += __shfl_xor_sync(0xffffffffu, a, off);
        b += __shfl_xor_sync(0xffffffffu, b, off);
    }
    if (lane == 0) { scratch[wid * 2] = a; scratch[wid * 2 + 1] = b; }
    __syncthreads();
    float ra = 0.f, rb = 0.f;
    #pragma unroll
    for (int w = 0; w < 8; ++w) { ra += scratch[w * 2]; rb += scratch[w * 2 + 1]; }
    __syncthreads();
    return make_float2(ra, rb);
}
} // namespace

__global__ __launch_bounds__(NT, 1) void memunit_kernel(
    const float* __restrict__ x,     const float* __restrict__ slot_init,
    const float* __restrict__ Wq,    const float* __restrict__ bq,
    const float* __restrict__ Wk,    const float* __restrict__ bk,
    const float* __restrict__ Wv,    const float* __restrict__ bv,
    const float* __restrict__ wg1W,  const float* __restrict__ wg1b,
    const float* __restrict__ wg2W,  const float* __restrict__ wg2b,
    const float* __restrict__ egW,   const float* __restrict__ egb,
    const float* __restrict__ wcW,   const float* __restrict__ wcb,
    const float* __restrict__ wclng, const float* __restrict__ wclnb,
    const float* __restrict__ fuW,   const float* __restrict__ fub,
    const float* __restrict__ fulng, const float* __restrict__ fulnb,
    const float* __restrict__ ong,   const float* __restrict__ onb,
    float* __restrict__ out)
{
    __shared__ float sM[D_][K_];      // M transposed: [feature i][slot j]
    __shared__ float scat[2 * D_];    // [x_t | r]
    __shared__ float sRed[8][32];     // cross-warp vector reduction scratch
    __shared__ float sBR[16];         // block_reduce_2 scratch
    __shared__ float sAttn[K_], sEvict[K_], sPers[K_], sAlpha[K_];
    __shared__ float sMean[K_], sRstd[K_];
    __shared__ float sNov[1];

    const int b    = blockIdx.x;
    const int o    = threadIdx.x;      // output-feature index this thread owns
    const int lane = o & 31;
    const int wid  = o >> 5;

    // Init state
    #pragma unroll
    for (int j = 0; j < K_; ++j) sM[o][j] = slot_init[j * D_ + o];
    if (o < K_) sPers[o] = 0.f;

    // Per-thread stationary vectors (one element each)
    const float bqo    = bq[o],   bko = bk[o],   bvo = bv[o];
    const float egbo   = egb[o],  wcbo = wcb[o];
    const float wclngo = wclng[o], wclnbo = wclnb[o];
    const float fubo   = fub[o],  fulngo = fulng[o], fulnbo = fulnb[o];
    const float wg1bo  = wg1b[o], wg2wo = wg2W[o],   wg2b0 = wg2b[0];
    const float ongo   = ong[o],  onbo  = onb[o];

    for (int t = 0; t < S_; ++t) {
        __syncthreads();  // prev-step M update / scat reads complete
        scat[o] = x[((size_t)t * B_ + b) * D_ + o];
        __syncthreads();

        // ---- Merged GEMMs over i = 0..255:
        //   q  += x_i * Wq[i,o]
        //   ce += x_i * egW[i,o]       (x-half of sq, slot-invariant)
        //   cw += x_i * wcW[i,o]
        //   k[j] += M[j,i]*Wk[i,o]; v[j] += M[j,i]*Wv[i,o]
        //   e[j] += M[j,i]*egW[256+i,o]; w[j] += M[j,i]*wcW[256+i,o]
        float accq = 0.f, ce = 0.f, cw = 0.f;
        float acck[K_], accv[K_], acce[K_], accw[K_];
        #pragma unroll
        for (int j = 0; j < K_; ++j) { acck[j]=0.f; accv[j]=0.f; acce[j]=0.f; accw[j]=0.f; }

        #pragma unroll 2
        for (int i = 0; i < D_; ++i) {
            float xv = scat[i];
            const float4* mr = reinterpret_cast<const float4*>(&sM[i][0]);
            float4 m0 = mr[0], m1 = mr[1], m2 = mr[2], m3 = mr[3];
            float wq_ = Wq[i * D_ + o];
            float wk_ = Wk[i * D_ + o];
            float wv_ = Wv[i * D_ + o];
            float weL = egW[i * D_ + o];
            float weH = egW[(D_ + i) * D_ + o];
            float wwL = wcW[i * D_ + o];
            float wwH = wcW[(D_ + i) * D_ + o];
            accq = fmaf(xv, wq_, accq);
            ce   = fmaf(xv, weL, ce);
            cw   = fmaf(xv, wwL, cw);
            float mv[K_] = {m0.x,m0.y,m0.z,m0.w, m1.x,m1.y,m1.z,m1.w,
                            m2.x,m2.y,m2.z,m2.w, m3.x,m3.y,m3.z,m3.w};
            #pragma unroll
            for (int j = 0; j < K_; ++j) {
                acck[j] = fmaf(mv[j], wk_, acck[j]);
                accv[j] = fmaf(mv[j], wv_, accv[j]);
                acce[j] = fmaf(mv[j], weH, acce[j]);
                accw[j] = fmaf(mv[j], wwH, accw[j]);
            }
        }

        // ---- attention logits: logit[j] = sum_o q_o * k[j,o]
        float qo = accq + bqo;
        float p[K_];
        #pragma unroll
        for (int j = 0; j < K_; ++j) p[j] = qo * (acck[j] + bko);
        #pragma unroll
        for (int off = 16; off; off >>= 1) {
            #pragma unroll
            for (int j = 0; j < K_; ++j) p[j] += __shfl_xor_sync(0xffffffffu, p[j], off);
        }
        if (lane == 0) {
            #pragma unroll
            for (int j = 0; j < K_; ++j) sRed[wid][j] = p[j];
        }
        __syncthreads();

        // ---- softmax over slots, pers momentum, evict softmax (lanes 0..15 of warp 0)
        if (o < K_) {
            float l = 0.f;
            #pragma unroll
            for (int w = 0; w < 8; ++w) l += sRed[w][o];
            l *= 0.0625f;                            // d^-0.5 = 1/16
            float mx = l;
            #pragma unroll
            for (int off = 8; off; off >>= 1) mx = fmaxf(mx, __shfl_xor_sync(0xffffu, mx, off, 16));
            float e = expf(l - mx);
            float s = e;
            #pragma unroll
            for (int off = 8; off; off >>= 1) s += __shfl_xor_sync(0xffffu, s, off, 16);
            float a = e / s;
            sAttn[o] = a;
            if (o == 0) sNov[0] = 1.f - 1.f / s;     // 1 - max(attn); max exp = 1
            float pr = MOMC * sPers[o] + (1.f - MOMC) * a;
            sPers[o] = pr;
            float el = -4.f * pr;
            float em = el;
            #pragma unroll
            for (int off = 8; off; off >>= 1) em = fmaxf(em, __shfl_xor_sync(0xffffu, em, off, 16));
            float ee = expf(el - em);
            float es = ee;
            #pragma unroll
            for (int off = 8; off; off >>= 1) es += __shfl_xor_sync(0xffffu, es, off, 16);
            sEvict[o] = ee / es;
        }
        __syncthreads();

        // ---- r = attn @ v ; build cat = [x | r]
        float r = 0.f;
        #pragma unroll
        for (int j = 0; j < K_; ++j) r = fmaf(sAttn[j], accv[j] + bvo, r);
        scat[D_ + o] = r;

        // ---- write candidate: gelu(wc pre-act), per-slot LN stats over d
        float g[K_], sg[K_], g2[K_];
        #pragma unroll
        for (int j = 0; j < K_; ++j) {
            g[j]  = geluf(accw[j] + cw + wcbo);
            sg[j] = g[j];
            g2[j] = g[j] * g[j];
        }
        #pragma unroll
        for (int off = 16; off; off >>= 1) {
            #pragma unroll
            for (int j = 0; j < K_; ++j) {
                sg[j] += __shfl_xor_sync(0xffffffffu, sg[j], off);
                g2[j] += __shfl_xor_sync(0xffffffffu, g2[j], off);
            }
        }
        if (lane == 0) {
            #pragma unroll
            for (int j = 0; j < K_; ++j) { sRed[wid][j] = sg[j]; sRed[wid][16 + j] = g2[j]; }
        }
        __syncthreads();
        if (o < K_) {
            float sm = 0.f, sq = 0.f;
            #pragma unroll
            for (int w = 0; w < 8; ++w) { sm += sRed[w][o]; sq += sRed[w][16 + o]; }
            float mean = sm * (1.f / D_);
            float var  = sq * (1.f / D_) - mean * mean;
            sMean[o] = mean;
            sRstd[o] = rsqrtf(var + EPSLN);
        }
        __syncthreads();  // scat[D..], sMean/sRstd ready

        // ---- fu / wg1 GEMMs over cat (512 inputs)
        float accf = 0.f, accg = 0.f;
        #pragma unroll 4
        for (int i = 0; i < 2 * D_; ++i) {
            float cv = scat[i];
            accf = fmaf(cv, fuW[i * D_ + o], accf);
            accg = fmaf(cv, wg1W[i * D_ + o], accg);
        }
        // out_t = LN(gelu(fu pre))
        float hf = geluf(accf + fubo);
        float2 fs = block_reduce_2(hf, hf * hf, sBR, lane, wid);
        float fmn = fs.x * (1.f / D_);
        float fvr = fs.y * (1.f / D_) - fmn * fmn;
        float outt = (hf - fmn) * rsqrtf(fvr + EPSLN) * fulngo + fulnbo;

        // g_w = sigmoid(gelu(wg1 pre) @ wg2 + b) * novelty
        float hg = geluf(accg + wg1bo);
        float2 ws = block_reduce_2(hg * wg2wo, 0.f, sBR, lane, wid);
        float gw = sigmf(ws.x + wg2b0) * sNov[0];

        if (o < K_) {
            sAlpha[o] = gw * sEvict[o];
            sPers[o] += sEvict[o] * gw * 0.1f;
        }

        // ---- x_aug output: LN(out_t + x_t)   (block_reduce_2 syncs make sAlpha visible)
        float u = outt + scat[o];
        float2 us = block_reduce_2(u, u * u, sBR, lane, wid);
        float um = us.x * (1.f / D_);
        float uv = us.y * (1.f / D_) - um * um;
        out[((size_t)t * B_ + b) * D_ + o] = (u - um) * rsqrtf(uv + EPSLN) * ongo + onbo;

        // ---- memory update: M = M*(1 - a*erase) + a*write
        #pragma unroll
        for (int j = 0; j < K_; ++j) {
            float er = sigmf(acce[j] + ce + egbo);
            float wr = (g[j] - sMean[j]) * sRstd[j] * wclngo + wclnbo;
            float al = sAlpha[j];
            sM[o][j] = sM[o][j] * (1.f - al * er) + al * wr;
        }
    }

    __syncthreads();
    // proto = transpose(M, (1,0,2)) : [K, B, d]
    #pragma unroll
    for (int j = 0; j < K_; ++j)
        out[(size_t)S_ * B_ * D_ + ((size_t)j * B_ + b) * D_ + o] = sM[o][j];
}

extern "C" void kernel_launch(void* const* d_in, const int* in_sizes, int n_in,
                              void* d_out, int out_size) {
    (void)in_sizes; (void)n_in; (void)out_size;
    memunit_kernel<<<B_, NT>>>(
        (const float*)d_in[0],  (const float*)d_in[1],
        (const float*)d_in[2],  (const float*)d_in[3],
        (const float*)d_in[4],  (const float*)d_in[5],
        (const float*)d_in[6],  (const float*)d_in[7],
        (const float*)d_in[8],  (const float*)d_in[9],
        (const float*)d_in[10], (const float*)d_in[11],
        (const float*)d_in[12], (const float*)d_in[13],
        (const float*)d_in[14], (const float*)d_in[15],
        (const float*)d_in[16], (const float*)d_in[17],
        (const float*)d_in[18], (const float*)d_in[19],
        (const float*)d_in[20], (const float*)d_in[21],
        (const float*)d_in[22], (const float*)d_in[23],
        (float*)d_out);
}

// round 4
// speedup vs baseline: 1.9855x; 1.9855x over previous
#include <cuda_runtime.h>
#include <math.h>
#include <stdint.h>

// MemoryUnit, Round 3: 2-CTA clusters per batch element (grid=128, all SMs),
// output-feature split with DSMEM exchanges; fp32 exact math.
// Fix vs R2: removed erroneous *0.5 on the B1 partial sums (butterfly over
// offsets {2,4,8,16} counts each output feature exactly once).

namespace {
constexpr int S_ = 2048;
constexpr int B_ = 64;
constexpr int D_ = 256;
constexpr int K_ = 16;
constexpr int NT = 256;
constexpr float EPSLN = 1e-5f;
constexpr float MOMC  = 0.9f;

__device__ __forceinline__ float geluf(float v) {
    return 0.5f * v * (1.0f + erff(v * 0.70710678118654752440f));
}
__device__ __forceinline__ float sigmf(float v) {
    return 1.0f / (1.0f + expf(-v));
}
__device__ __forceinline__ uint32_t smem_u32(const void* p) {
    return (uint32_t)__cvta_generic_to_shared(const_cast<void*>(p));
}
__device__ __forceinline__ uint32_t peer_addr(uint32_t la, uint32_t peer) {
    uint32_t ra;
    asm("mapa.shared::cluster.u32 %0, %1, %2;" : "=r"(ra) : "r"(la), "r"(peer));
    return ra;
}
__device__ __forceinline__ void st_peer_f32(uint32_t ra, float v) {
    asm volatile("st.shared::cluster.f32 [%0], %1;" :: "r"(ra), "f"(v) : "memory");
}
__device__ __forceinline__ void st_peer_f128(uint32_t ra, float4 v) {
    asm volatile("st.shared::cluster.v4.f32 [%0], {%1,%2,%3,%4};"
                 :: "r"(ra), "f"(v.x), "f"(v.y), "f"(v.z), "f"(v.w) : "memory");
}
__device__ __forceinline__ void cluster_sync_() {
    asm volatile("barrier.cluster.arrive.aligned;\n\t"
                 "barrier.cluster.wait.aligned;" ::: "memory");
}
} // namespace

__global__ __launch_bounds__(NT, 1) __cluster_dims__(2, 1, 1)
void memunit_kernel(
    const float* __restrict__ x,     const float* __restrict__ slot_init,
    const float* __restrict__ Wq,    const float* __restrict__ bq,
    const float* __restrict__ Wk,    const float* __restrict__ bk,
    const float* __restrict__ Wv,    const float* __restrict__ bv,
    const float* __restrict__ wg1W,  const float* __restrict__ wg1b,
    const float* __restrict__ wg2W,  const float* __restrict__ wg2b,
    const float* __restrict__ egW,   const float* __restrict__ egb,
    const float* __restrict__ wcW,   const float* __restrict__ wcb,
    const float* __restrict__ wclng, const float* __restrict__ wclnb,
    const float* __restrict__ fuW,   const float* __restrict__ fub,
    const float* __restrict__ fulng, const float* __restrict__ fulnb,
    const float* __restrict__ ong,   const float* __restrict__ onb,
    float* __restrict__ out)
{
    __shared__ float sM[D_][K_];      // full M, feature-major; own half updated
                                      // locally, peer half mirrored via DSMEM
    __shared__ float scat[2 * D_];    // [x_t | r] (r half-filled by peer)
    __shared__ float sW[8][48];       // per-warp partials: logits|gsum|gsq
    __shared__ float sLoc[48];        // my half-sums
    __shared__ float eL[48];          // peer half-sums (DSMEM-written)
    __shared__ float eF[3];           // peer fu-LN/wg2 partials
    __shared__ float eU[2];           // peer out-LN partials
    __shared__ float sBR[8][4];       // block-reduce scratch
    __shared__ float sAttn[K_], sEvict[K_], sPers[K_], sMean[K_], sRstd[K_];
    __shared__ float sNov;

    const int tid  = threadIdx.x;
    const int lane = tid & 31;
    const int wid  = tid >> 5;
    const int ih   = tid & 1;        // which half of the reduction dim
    const int ol   = tid >> 1;       // local output feature 0..127
    uint32_t rank;
    asm("mov.u32 %0, %%cluster_ctarank;" : "=r"(rank));
    const uint32_t peer = rank ^ 1u;
    const int b  = blockIdx.x >> 1;
    const int og = (int)rank * 128 + ol;   // global output feature

    // init state (both CTAs hold a full copy of M)
    #pragma unroll
    for (int j = 0; j < K_; ++j) sM[tid][j] = slot_init[j * D_ + tid];
    if (tid < K_) sPers[tid] = 0.f;

    const float bqo    = bq[og],    bko    = bk[og],    bvo   = bv[og];
    const float egbo   = egb[og],   wcbo   = wcb[og];
    const float wclngo = wclng[og], wclnbo = wclnb[og];
    const float fubo   = fub[og],   fulngo = fulng[og], fulnbo = fulnb[og];
    const float wg1bo  = wg1b[og],  wg2wo  = wg2W[og],  wg2b0  = wg2b[0];
    const float ongo   = ong[og],   onbo   = onb[og];

    const float* pWq = Wq   + og;
    const float* pWk = Wk   + og;
    const float* pWv = Wv   + og;
    const float* pEg = egW  + og;
    const float* pWc = wcW  + og;
    const float* pFu = fuW  + og;
    const float* pG1 = wg1W + og;

    for (int t = 0; t < S_; ++t) {
        scat[tid] = x[((size_t)t * B_ + b) * D_ + tid];
        __syncthreads();

        // ---- merged GEMMs, reduction split over i-halves (ih) ----
        float accq = 0.f, ce = 0.f, cw = 0.f;
        float acck[K_], accv[K_], acce[K_], accw[K_];
        #pragma unroll
        for (int j = 0; j < K_; ++j) { acck[j]=0.f; accv[j]=0.f; acce[j]=0.f; accw[j]=0.f; }

        const int i0 = ih << 7;
        #pragma unroll 4
        for (int ii = 0; ii < 128; ++ii) {
            const int i   = i0 + ii;
            const int wix = i * D_;
            const float xv = scat[i];
            const float4* mr = reinterpret_cast<const float4*>(sM[i]);
            const float4 m0 = mr[0], m1 = mr[1], m2 = mr[2], m3 = mr[3];
            const float wq_ = pWq[wix], wk_ = pWk[wix], wv_ = pWv[wix];
            const float weL_ = pEg[wix], weH_ = pEg[wix + D_ * D_];
            const float wwL_ = pWc[wix], wwH_ = pWc[wix + D_ * D_];
            accq = fmaf(xv, wq_, accq);
            ce   = fmaf(xv, weL_, ce);
            cw   = fmaf(xv, wwL_, cw);
            const float mv[K_] = {m0.x,m0.y,m0.z,m0.w, m1.x,m1.y,m1.z,m1.w,
                                  m2.x,m2.y,m2.z,m2.w, m3.x,m3.y,m3.z,m3.w};
            #pragma unroll
            for (int j = 0; j < K_; ++j) {
                acck[j] = fmaf(mv[j], wk_,  acck[j]);
                accv[j] = fmaf(mv[j], wv_,  accv[j]);
                acce[j] = fmaf(mv[j], weH_, acce[j]);
                accw[j] = fmaf(mv[j], wwH_, accw[j]);
            }
        }
        // pair-reduce the two i-halves (lanes 2k / 2k+1)
        accq += __shfl_xor_sync(0xffffffffu, accq, 1);
        ce   += __shfl_xor_sync(0xffffffffu, ce,   1);
        cw   += __shfl_xor_sync(0xffffffffu, cw,   1);
        #pragma unroll
        for (int j = 0; j < K_; ++j) {
            acck[j] += __shfl_xor_sync(0xffffffffu, acck[j], 1);
            accv[j] += __shfl_xor_sync(0xffffffffu, accv[j], 1);
            acce[j] += __shfl_xor_sync(0xffffffffu, acce[j], 1);
            accw[j] += __shfl_xor_sync(0xffffffffu, accw[j], 1);
        }

        // ---- logits + write-candidate LN partials (over my 128 o) ----
        const float qo = accq + bqo;
        float p[K_], g[K_], gs[K_], gq[K_];
        #pragma unroll
        for (int j = 0; j < K_; ++j) {
            p[j]  = qo * (acck[j] + bko);
            g[j]  = geluf(accw[j] + cw + wcbo);
            gs[j] = g[j];
            gq[j] = g[j] * g[j];
        }
        #pragma unroll
        for (int off = 2; off <= 16; off <<= 1) {
            #pragma unroll
            for (int j = 0; j < K_; ++j) {
                p[j]  += __shfl_xor_sync(0xffffffffu, p[j],  off);
                gs[j] += __shfl_xor_sync(0xffffffffu, gs[j], off);
                gq[j] += __shfl_xor_sync(0xffffffffu, gq[j], off);
            }
        }
        if (lane == 0) {
            #pragma unroll
            for (int j = 0; j < K_; ++j) {
                sW[wid][j] = p[j]; sW[wid][16 + j] = gs[j]; sW[wid][32 + j] = gq[j];
            }
        }
        __syncthreads();
        if (tid < 48) {
            float s = 0.f;
            #pragma unroll
            for (int w = 0; w < 8; ++w) s += sW[w][tid];
            // NOTE: butterfly above covered each output feature exactly once
            // (offsets {2,4,8,16} span only same-parity lanes) -> no 0.5 factor.
            sLoc[tid] = s;
            st_peer_f32(peer_addr(smem_u32(&eL[tid]), peer), s);
        }
        cluster_sync_();   // B1: logits + g-stats halves exchanged

        // ---- softmax / pers / evict / write-LN stats (slots = lanes 0..15) ----
        if (tid < K_) {
            float l = (sLoc[tid] + eL[tid]) * 0.0625f;   // * d^-0.5
            float mx = l;
            #pragma unroll
            for (int off = 8; off; off >>= 1) mx = fmaxf(mx, __shfl_xor_sync(0xffffu, mx, off, 16));
            float e = expf(l - mx);
            float s = e;
            #pragma unroll
            for (int off = 8; off; off >>= 1) s += __shfl_xor_sync(0xffffu, s, off, 16);
            float a = e / s;
            sAttn[tid] = a;
            if (tid == 0) sNov = 1.f - 1.f / s;          // 1 - max(attn)
            float pr = MOMC * sPers[tid] + (1.f - MOMC) * a;
            sPers[tid] = pr;
            float el = -4.f * pr, em = el;
            #pragma unroll
            for (int off = 8; off; off >>= 1) em = fmaxf(em, __shfl_xor_sync(0xffffu, em, off, 16));
            float ee = expf(el - em);
            float es = ee;
            #pragma unroll
            for (int off = 8; off; off >>= 1) es += __shfl_xor_sync(0xffffu, es, off, 16);
            sEvict[tid] = ee / es;
            float gsum = sLoc[16 + tid] + eL[16 + tid];
            float gsq  = sLoc[32 + tid] + eL[32 + tid];
            float mean = gsum * (1.f / D_);
            float var  = gsq * (1.f / D_) - mean * mean;
            sMean[tid] = mean;
            sRstd[tid] = rsqrtf(var + EPSLN);
        }
        __syncthreads();

        // ---- r = attn @ v ; publish my r half to both CTAs ----
        float r = 0.f;
        #pragma unroll
        for (int j = 0; j < K_; ++j) r = fmaf(sAttn[j], accv[j] + bvo, r);
        if (ih == 0) scat[D_ + og] = r;
        else         st_peer_f32(peer_addr(smem_u32(&scat[D_ + og]), peer), r);
        cluster_sync_();   // B2: full cat = [x | r] present in both CTAs

        // ---- fu / wg1 GEMMs over cat (512 inputs, split over ih) ----
        float accf = 0.f, accg = 0.f;
        const int c0 = ih << 8;
        #pragma unroll 4
        for (int ii = 0; ii < 256; ++ii) {
            const int i = c0 + ii;
            const float cv = scat[i];
            accf = fmaf(cv, pFu[i * D_], accf);
            accg = fmaf(cv, pG1[i * D_], accg);
        }
        accf += __shfl_xor_sync(0xffffffffu, accf, 1);
        accg += __shfl_xor_sync(0xffffffffu, accg, 1);
        const float hf = geluf(accf + fubo);
        const float hg = geluf(accg + wg1bo);

        float a0 = hf, a1 = hf * hf, a2 = hg * wg2wo;
        #pragma unroll
        for (int off = 1; off < 32; off <<= 1) {
            a0 += __shfl_xor_sync(0xffffffffu, a0, off);
            a1 += __shfl_xor_sync(0xffffffffu, a1, off);
            a2 += __shfl_xor_sync(0xffffffffu, a2, off);
        }
        if (lane == 0) { sBR[wid][0] = a0; sBR[wid][1] = a1; sBR[wid][2] = a2; }
        __syncthreads();
        float lf0 = 0.f, lf1 = 0.f, lf2 = 0.f;
        #pragma unroll
        for (int w = 0; w < 8; ++w) { lf0 += sBR[w][0]; lf1 += sBR[w][1]; lf2 += sBR[w][2]; }
        lf0 *= 0.5f; lf1 *= 0.5f; lf2 *= 0.5f;   // full-warp butterfly counts each o twice
        if (tid == 0) {
            uint32_t ra = peer_addr(smem_u32(&eF[0]), peer);
            st_peer_f32(ra, lf0); st_peer_f32(ra + 4, lf1); st_peer_f32(ra + 8, lf2);
        }
        cluster_sync_();   // B3: fu-LN + wg2 partials exchanged

        const float fsum = lf0 + eF[0], fsq = lf1 + eF[1], wgs = lf2 + eF[2];
        const float fmn  = fsum * (1.f / D_);
        const float fvr  = fsq * (1.f / D_) - fmn * fmn;
        const float outt = (hf - fmn) * rsqrtf(fvr + EPSLN) * fulngo + fulnbo;
        const float gw   = sigmf(wgs + wg2b0) * sNov;

        if (tid < K_) sPers[tid] += sEvict[tid] * gw * 0.1f;

        // ---- out-LN partials (exchange overlapped with M mirror write) ----
        const float u = outt + scat[og];
        float u0 = u, u1 = u * u;
        #pragma unroll
        for (int off = 1; off < 32; off <<= 1) {
            u0 += __shfl_xor_sync(0xffffffffu, u0, off);
            u1 += __shfl_xor_sync(0xffffffffu, u1, off);
        }
        if (lane == 0) { sBR[wid][0] = u0; sBR[wid][1] = u1; }
        __syncthreads();
        float lu0 = 0.f, lu1 = 0.f;
        #pragma unroll
        for (int w = 0; w < 8; ++w) { lu0 += sBR[w][0]; lu1 += sBR[w][1]; }
        lu0 *= 0.5f; lu1 *= 0.5f;                 // full-warp butterfly: each o twice
        if (tid == 0) {
            uint32_t ra = peer_addr(smem_u32(&eU[0]), peer);
            st_peer_f32(ra, lu0); st_peer_f32(ra + 4, lu1);
        }

        // ---- memory update: local write (ih0) + peer mirror (ih1) ----
        float nm[K_];
        #pragma unroll
        for (int j = 0; j < K_; ++j) {
            const float er = sigmf(acce[j] + ce + egbo);
            const float wr = (g[j] - sMean[j]) * sRstd[j] * wclngo + wclnbo;
            const float al = gw * sEvict[j];
            nm[j] = sM[og][j] * (1.f - al * er) + al * wr;
        }
        if (ih == 0) {
            float4* rowp = reinterpret_cast<float4*>(sM[og]);
            rowp[0] = make_float4(nm[0],  nm[1],  nm[2],  nm[3]);
            rowp[1] = make_float4(nm[4],  nm[5],  nm[6],  nm[7]);
            rowp[2] = make_float4(nm[8],  nm[9],  nm[10], nm[11]);
            rowp[3] = make_float4(nm[12], nm[13], nm[14], nm[15]);
        } else {
            uint32_t ra = peer_addr(smem_u32(&sM[og][0]), peer);
            st_peer_f128(ra,      make_float4(nm[0],  nm[1],  nm[2],  nm[3]));
            st_peer_f128(ra + 16, make_float4(nm[4],  nm[5],  nm[6],  nm[7]));
            st_peer_f128(ra + 32, make_float4(nm[8],  nm[9],  nm[10], nm[11]));
            st_peer_f128(ra + 48, make_float4(nm[12], nm[13], nm[14], nm[15]));
        }
        cluster_sync_();   // B4: out-LN partials + peer M half visible

        const float usum = lu0 + eU[0], usq = lu1 + eU[1];
        const float um = usum * (1.f / D_);
        const float uv = usq * (1.f / D_) - um * um;
        if (ih == 0)
            out[((size_t)t * B_ + b) * D_ + og] = (u - um) * rsqrtf(uv + EPSLN) * ongo + onbo;
    }

    // proto = transpose(M, (1,0,2)) : [K, B, d]; each CTA writes its own features
    if (ih == 0) {
        #pragma unroll
        for (int j = 0; j < K_; ++j)
            out[(size_t)S_ * B_ * D_ + ((size_t)j * B_ + b) * D_ + og] = sM[og][j];
    }
}

extern "C" void kernel_launch(void* const* d_in, const int* in_sizes, int n_in,
                              void* d_out, int out_size) {
    (void)in_sizes; (void)n_in; (void)out_size;
    memunit_kernel<<<2 * B_, NT>>>(
        (const float*)d_in[0],  (const float*)d_in[1],
        (const float*)d_in[2],  (const float*)d_in[3],
        (const float*)d_in[4],  (const float*)d_in[5],
        (const float*)d_in[6],  (const float*)d_in[7],
        (const float*)d_in[8],  (const float*)d_in[9],
        (const float*)d_in[10], (const float*)d_in[11],
        (const float*)d_in[12], (const float*)d_in[13],
        (const float*)d_in[14], (const float*)d_in[15],
        (const float*)d_in[16], (const float*)d_in[17],
        (const float*)d_in[18], (const float*)d_in[19],
        (const float*)d_in[20], (const float*)d_in[21],
        (const float*)d_in[22], (const float*)d_in[23],
        (float*)d_out);
}

// round 5
// speedup vs baseline: 2.4680x; 1.2430x over previous
#include <cuda_runtime.h>
#include <math.h>
#include <stdint.h>

// MemoryUnit, Round 4: 2-CTA cluster per batch element, o-PAIR threads
// (LDG.64 weight loads) + matrix-group warp specialization:
//   warps 0-3 (group A): q,k,v GEMMs + attention/softmax/fu/out epilogues
//   warps 4-7 (group B): eg,wc GEMMs + write-candidate LN + M update
// All butterflies use parity offsets {2,4,8,16} -> each o counted once.

namespace {
constexpr int S_ = 2048;
constexpr int B_ = 64;
constexpr int D_ = 256;
constexpr int K_ = 16;
constexpr int NT = 256;
constexpr float EPSLN = 1e-5f;
constexpr float MOMC  = 0.9f;

__device__ __forceinline__ float geluf(float v) {
    return 0.5f * v * (1.0f + erff(v * 0.70710678118654752440f));
}
__device__ __forceinline__ float sigmf(float v) {
    return 1.0f / (1.0f + expf(-v));
}
__device__ __forceinline__ uint32_t smem_u32(const void* p) {
    return (uint32_t)__cvta_generic_to_shared(const_cast<void*>(p));
}
__device__ __forceinline__ uint32_t peer_addr(uint32_t la, uint32_t peer) {
    uint32_t ra;
    asm("mapa.shared::cluster.u32 %0, %1, %2;" : "=r"(ra) : "r"(la), "r"(peer));
    return ra;
}
__device__ __forceinline__ void st_peer_f32(uint32_t ra, float v) {
    asm volatile("st.shared::cluster.f32 [%0], %1;" :: "r"(ra), "f"(v) : "memory");
}
__device__ __forceinline__ void st_peer_f64(uint32_t ra, float a, float b) {
    asm volatile("st.shared::cluster.v2.f32 [%0], {%1,%2};"
                 :: "r"(ra), "f"(a), "f"(b) : "memory");
}
__device__ __forceinline__ void st_peer_f128(uint32_t ra, float4 v) {
    asm volatile("st.shared::cluster.v4.f32 [%0], {%1,%2,%3,%4};"
                 :: "r"(ra), "f"(v.x), "f"(v.y), "f"(v.z), "f"(v.w) : "memory");
}
__device__ __forceinline__ void cluster_sync_() {
    asm volatile("barrier.cluster.arrive.aligned;\n\t"
                 "barrier.cluster.wait.aligned;" ::: "memory");
}
__device__ __forceinline__ float2 ld2(const float* p) {
    return *reinterpret_cast<const float2*>(p);
}
} // namespace

__global__ __launch_bounds__(NT, 1) __cluster_dims__(2, 1, 1)
void memunit_kernel(
    const float* __restrict__ x,     const float* __restrict__ slot_init,
    const float* __restrict__ Wq,    const float* __restrict__ bq,
    const float* __restrict__ Wk,    const float* __restrict__ bk,
    const float* __restrict__ Wv,    const float* __restrict__ bv,
    const float* __restrict__ wg1W,  const float* __restrict__ wg1b,
    const float* __restrict__ wg2W,  const float* __restrict__ wg2b,
    const float* __restrict__ egW,   const float* __restrict__ egb,
    const float* __restrict__ wcW,   const float* __restrict__ wcb,
    const float* __restrict__ wclng, const float* __restrict__ wclnb,
    const float* __restrict__ fuW,   const float* __restrict__ fub,
    const float* __restrict__ fulng, const float* __restrict__ fulnb,
    const float* __restrict__ ong,   const float* __restrict__ onb,
    float* __restrict__ out)
{
    __shared__ float sM[D_][K_];      // full M (feature-major), mirrored via DSMEM
    __shared__ float scat[2 * D_];    // [x_t | r]
    __shared__ float sWA[4][K_];      // A-warp logit partials
    __shared__ float sWB[4][2 * K_];  // B-warp gsum|gsq partials
    __shared__ float sLoc[48];        // my half-sums (logits|gsum|gsq)
    __shared__ float eL[48];          // peer half-sums
    __shared__ float sFB[64][4];      // group-B fu/wg1 partials per o-pair
    __shared__ float sBR[4][4];       // A-warp block-reduce scratch
    __shared__ float eF[3], eU[2];    // peer fu-LN/wg2 and out-LN partials
    __shared__ float sAttn[K_], sEvict[K_], sPers[K_], sMean[K_], sRstd[K_];
    __shared__ float sNov, sGW;

    const int tid  = threadIdx.x;
    const int lane = tid & 31;
    const int wid  = tid >> 5;
    const int mh   = wid >> 2;        // 0 = group A (q,k,v), 1 = group B (eg,wc)
    const int gt   = tid & 127;
    const int ih   = gt & 1;          // reduction half
    const int op   = gt >> 1;         // o-pair index 0..63
    uint32_t rank;
    asm("mov.u32 %0, %%cluster_ctarank;" : "=r"(rank));
    const uint32_t peer = rank ^ 1u;
    const int b  = blockIdx.x >> 1;
    const int og = (int)rank * 128 + op * 2;   // first of this thread's 2 outputs

    #pragma unroll
    for (int j = 0; j < K_; ++j) sM[tid][j] = slot_init[j * D_ + tid];
    if (tid < K_) sPers[tid] = 0.f;

    // per-thread constant pairs
    const float2 bqv = ld2(bq + og), bkv = ld2(bk + og), bvv = ld2(bv + og);
    const float2 egbv = ld2(egb + og), wcbv = ld2(wcb + og);
    const float2 wclngv = ld2(wclng + og), wclnbv = ld2(wclnb + og);
    const float2 fubv = ld2(fub + og), fulngv = ld2(fulng + og), fulnbv = ld2(fulnb + og);
    const float2 wg1bv = ld2(wg1b + og), wg2wv = ld2(wg2W + og);
    const float  wg2b0 = wg2b[0];
    const float2 ongv = ld2(ong + og), onbv = ld2(onb + og);

    for (int t = 0; t < S_; ++t) {
        scat[tid] = x[((size_t)t * B_ + b) * D_ + tid];
        __syncthreads();

        const int i0 = ih << 7;
        float av0[K_], av1[K_];           // group A: v accumulators (live to r)
        float ae0[K_], ae1[K_];           // group B: erase accumulators
        float g0[K_], g1[K_];             // group B: gelu(write pre-act)
        float ce0 = 0.f, ce1 = 0.f;

        if (mh == 0) {
            // ---- group A: q,k,v ----
            float aq0 = 0.f, aq1 = 0.f;
            float ak0[K_], ak1[K_];
            #pragma unroll
            for (int j = 0; j < K_; ++j) { ak0[j]=0.f; ak1[j]=0.f; av0[j]=0.f; av1[j]=0.f; }
            #pragma unroll 4
            for (int ii = 0; ii < 128; ++ii) {
                const int i = i0 + ii;
                const int wix = i * D_ + og;
                const float xv = scat[i];
                const float4* mr = reinterpret_cast<const float4*>(sM[i]);
                const float4 m0 = mr[0], m1 = mr[1], m2 = mr[2], m3 = mr[3];
                const float2 wq = ld2(Wq + wix);
                const float2 wk = ld2(Wk + wix);
                const float2 wv = ld2(Wv + wix);
                aq0 = fmaf(xv, wq.x, aq0); aq1 = fmaf(xv, wq.y, aq1);
                const float mv[K_] = {m0.x,m0.y,m0.z,m0.w, m1.x,m1.y,m1.z,m1.w,
                                      m2.x,m2.y,m2.z,m2.w, m3.x,m3.y,m3.z,m3.w};
                #pragma unroll
                for (int j = 0; j < K_; ++j) {
                    ak0[j] = fmaf(mv[j], wk.x, ak0[j]);
                    ak1[j] = fmaf(mv[j], wk.y, ak1[j]);
                    av0[j] = fmaf(mv[j], wv.x, av0[j]);
                    av1[j] = fmaf(mv[j], wv.y, av1[j]);
                }
            }
            aq0 += __shfl_xor_sync(0xffffffffu, aq0, 1);
            aq1 += __shfl_xor_sync(0xffffffffu, aq1, 1);
            #pragma unroll
            for (int j = 0; j < K_; ++j) {
                ak0[j] += __shfl_xor_sync(0xffffffffu, ak0[j], 1);
                ak1[j] += __shfl_xor_sync(0xffffffffu, ak1[j], 1);
                av0[j] += __shfl_xor_sync(0xffffffffu, av0[j], 1);
                av1[j] += __shfl_xor_sync(0xffffffffu, av1[j], 1);
            }
            // logits: p[j] = q.o0*k[j].o0 + q.o1*k[j].o1 over my 2 outputs
            const float q0 = aq0 + bqv.x, q1 = aq1 + bqv.y;
            float p[K_];
            #pragma unroll
            for (int j = 0; j < K_; ++j)
                p[j] = q0 * (ak0[j] + bkv.x) + q1 * (ak1[j] + bkv.y);
            #pragma unroll
            for (int off = 2; off <= 16; off <<= 1) {
                #pragma unroll
                for (int j = 0; j < K_; ++j)
                    p[j] += __shfl_xor_sync(0xffffffffu, p[j], off);
            }
            if (lane == 0) {
                #pragma unroll
                for (int j = 0; j < K_; ++j) sWA[wid][j] = p[j];
            }
        } else {
            // ---- group B: eg, wc ----
            float cw0 = 0.f, cw1 = 0.f;
            float aw0[K_], aw1[K_];
            #pragma unroll
            for (int j = 0; j < K_; ++j) { ae0[j]=0.f; ae1[j]=0.f; aw0[j]=0.f; aw1[j]=0.f; }
            #pragma unroll 4
            for (int ii = 0; ii < 128; ++ii) {
                const int i = i0 + ii;
                const int wix = i * D_ + og;
                const float xv = scat[i];
                const float4* mr = reinterpret_cast<const float4*>(sM[i]);
                const float4 m0 = mr[0], m1 = mr[1], m2 = mr[2], m3 = mr[3];
                const float2 weL = ld2(egW + wix);
                const float2 weH = ld2(egW + wix + D_ * D_);
                const float2 wwL = ld2(wcW + wix);
                const float2 wwH = ld2(wcW + wix + D_ * D_);
                ce0 = fmaf(xv, weL.x, ce0); ce1 = fmaf(xv, weL.y, ce1);
                cw0 = fmaf(xv, wwL.x, cw0); cw1 = fmaf(xv, wwL.y, cw1);
                const float mv[K_] = {m0.x,m0.y,m0.z,m0.w, m1.x,m1.y,m1.z,m1.w,
                                      m2.x,m2.y,m2.z,m2.w, m3.x,m3.y,m3.z,m3.w};
                #pragma unroll
                for (int j = 0; j < K_; ++j) {
                    ae0[j] = fmaf(mv[j], weH.x, ae0[j]);
                    ae1[j] = fmaf(mv[j], weH.y, ae1[j]);
                    aw0[j] = fmaf(mv[j], wwH.x, aw0[j]);
                    aw1[j] = fmaf(mv[j], wwH.y, aw1[j]);
                }
            }
            ce0 += __shfl_xor_sync(0xffffffffu, ce0, 1);
            ce1 += __shfl_xor_sync(0xffffffffu, ce1, 1);
            cw0 += __shfl_xor_sync(0xffffffffu, cw0, 1);
            cw1 += __shfl_xor_sync(0xffffffffu, cw1, 1);
            #pragma unroll
            for (int j = 0; j < K_; ++j) {
                ae0[j] += __shfl_xor_sync(0xffffffffu, ae0[j], 1);
                ae1[j] += __shfl_xor_sync(0xffffffffu, ae1[j], 1);
                aw0[j] += __shfl_xor_sync(0xffffffffu, aw0[j], 1);
                aw1[j] += __shfl_xor_sync(0xffffffffu, aw1[j], 1);
            }
            // write candidate gelu + per-slot LN partials over my 2 outputs
            float gs[K_], gq[K_];
            #pragma unroll
            for (int j = 0; j < K_; ++j) {
                g0[j] = geluf(aw0[j] + cw0 + wcbv.x);
                g1[j] = geluf(aw1[j] + cw1 + wcbv.y);
                gs[j] = g0[j] + g1[j];
                gq[j] = g0[j] * g0[j] + g1[j] * g1[j];
            }
            #pragma unroll
            for (int off = 2; off <= 16; off <<= 1) {
                #pragma unroll
                for (int j = 0; j < K_; ++j) {
                    gs[j] += __shfl_xor_sync(0xffffffffu, gs[j], off);
                    gq[j] += __shfl_xor_sync(0xffffffffu, gq[j], off);
                }
            }
            if (lane == 0) {
                #pragma unroll
                for (int j = 0; j < K_; ++j) {
                    sWB[wid - 4][j] = gs[j];
                    sWB[wid - 4][K_ + j] = gq[j];
                }
            }
        }
        __syncthreads();

        // combine 4 warps per quantity, exchange halves with peer CTA
        if (tid < K_) {
            float s = sWA[0][tid] + sWA[1][tid] + sWA[2][tid] + sWA[3][tid];
            sLoc[tid] = s;
            st_peer_f32(peer_addr(smem_u32(&eL[tid]), peer), s);
        } else if (tid < 48) {
            const int j = tid - K_;
            float s = sWB[0][j] + sWB[1][j] + sWB[2][j] + sWB[3][j];
            sLoc[tid] = s;
            st_peer_f32(peer_addr(smem_u32(&eL[tid]), peer), s);
        }
        cluster_sync_();   // B1

        // softmax / pers / evict / write-LN stats (lanes 0..15)
        if (tid < K_) {
            float l = (sLoc[tid] + eL[tid]) * 0.0625f;
            float mx = l;
            #pragma unroll
            for (int off = 8; off; off >>= 1) mx = fmaxf(mx, __shfl_xor_sync(0xffffu, mx, off, 16));
            float e = expf(l - mx);
            float s = e;
            #pragma unroll
            for (int off = 8; off; off >>= 1) s += __shfl_xor_sync(0xffffu, s, off, 16);
            float a = e / s;
            sAttn[tid] = a;
            if (tid == 0) sNov = 1.f - 1.f / s;
            float pr = MOMC * sPers[tid] + (1.f - MOMC) * a;
            sPers[tid] = pr;
            float el = -4.f * pr, em = el;
            #pragma unroll
            for (int off = 8; off; off >>= 1) em = fmaxf(em, __shfl_xor_sync(0xffffu, em, off, 16));
            float ee = expf(el - em);
            float es = ee;
            #pragma unroll
            for (int off = 8; off; off >>= 1) es += __shfl_xor_sync(0xffffu, es, off, 16);
            sEvict[tid] = ee / es;
            const float gsum = sLoc[K_ + tid] + eL[K_ + tid];
            const float gsq  = sLoc[2 * K_ + tid] + eL[2 * K_ + tid];
            const float mean = gsum * (1.f / D_);
            const float var  = gsq * (1.f / D_) - mean * mean;
            sMean[tid] = mean;
            sRstd[tid] = rsqrtf(var + EPSLN);
        }
        __syncthreads();

        // r = attn @ v (group A), publish both halves of r
        if (mh == 0) {
            float r0 = 0.f, r1 = 0.f;
            #pragma unroll
            for (int j = 0; j < K_; ++j) {
                r0 = fmaf(sAttn[j], av0[j] + bvv.x, r0);
                r1 = fmaf(sAttn[j], av1[j] + bvv.y, r1);
            }
            if (ih == 0) { scat[D_ + og] = r0; scat[D_ + og + 1] = r1; }
            else st_peer_f64(peer_addr(smem_u32(&scat[D_ + og]), peer), r0, r1);
        }
        cluster_sync_();   // B2: full cat present in both CTAs

        // fu / wg1 over cat: 4-way split of the 512-input dim (ih x group)
        float af0 = 0.f, af1 = 0.f, ag0 = 0.f, ag1 = 0.f;
        const int c0 = (ih + 2 * mh) << 7;
        #pragma unroll 4
        for (int ii = 0; ii < 128; ++ii) {
            const int i = c0 + ii;
            const int wix = i * D_ + og;
            const float cv = scat[i];
            const float2 wf = ld2(fuW + wix);
            const float2 wg = ld2(wg1W + wix);
            af0 = fmaf(cv, wf.x, af0); af1 = fmaf(cv, wf.y, af1);
            ag0 = fmaf(cv, wg.x, ag0); ag1 = fmaf(cv, wg.y, ag1);
        }
        af0 += __shfl_xor_sync(0xffffffffu, af0, 1);
        af1 += __shfl_xor_sync(0xffffffffu, af1, 1);
        ag0 += __shfl_xor_sync(0xffffffffu, ag0, 1);
        ag1 += __shfl_xor_sync(0xffffffffu, ag1, 1);
        if (mh == 1 && ih == 0) {
            sFB[op][0] = af0; sFB[op][1] = af1; sFB[op][2] = ag0; sFB[op][3] = ag1;
        }
        __syncthreads();

        float hf0 = 0.f, hf1 = 0.f, u0v = 0.f, u1v = 0.f;
        if (mh == 0) {
            af0 += sFB[op][0]; af1 += sFB[op][1];
            ag0 += sFB[op][2]; ag1 += sFB[op][3];
            hf0 = geluf(af0 + fubv.x);
            hf1 = geluf(af1 + fubv.y);
            const float hg0 = geluf(ag0 + wg1bv.x);
            const float hg1 = geluf(ag1 + wg1bv.y);
            float a0 = hf0 + hf1;
            float a1 = hf0 * hf0 + hf1 * hf1;
            float a2 = hg0 * wg2wv.x + hg1 * wg2wv.y;
            #pragma unroll
            for (int off = 2; off <= 16; off <<= 1) {
                a0 += __shfl_xor_sync(0xffffffffu, a0, off);
                a1 += __shfl_xor_sync(0xffffffffu, a1, off);
                a2 += __shfl_xor_sync(0xffffffffu, a2, off);
            }
            if (lane == 0) { sBR[wid][0] = a0; sBR[wid][1] = a1; sBR[wid][2] = a2; }
        }
        __syncthreads();
        float lf0 = 0.f, lf1 = 0.f, lf2 = 0.f;
        if (mh == 0) {
            #pragma unroll
            for (int w = 0; w < 4; ++w) { lf0 += sBR[w][0]; lf1 += sBR[w][1]; lf2 += sBR[w][2]; }
            if (tid == 0) {
                uint32_t ra = peer_addr(smem_u32(&eF[0]), peer);
                st_peer_f32(ra, lf0); st_peer_f32(ra + 4, lf1); st_peer_f32(ra + 8, lf2);
            }
        }
        cluster_sync_();   // B3

        if (mh == 0) {
            const float fsum = lf0 + eF[0], fsq = lf1 + eF[1], wgs = lf2 + eF[2];
            const float fmn = fsum * (1.f / D_);
            const float fvr = fsq * (1.f / D_) - fmn * fmn;
            const float frs = rsqrtf(fvr + EPSLN);
            const float outt0 = (hf0 - fmn) * frs * fulngv.x + fulnbv.x;
            const float outt1 = (hf1 - fmn) * frs * fulngv.y + fulnbv.y;
            const float gw = sigmf(wgs + wg2b0) * sNov;
            if (tid == 0) sGW = gw;
            if (tid < K_) sPers[tid] += sEvict[tid] * gw * 0.1f;
            u0v = outt0 + scat[og];
            u1v = outt1 + scat[og + 1];
            float b0 = u0v + u1v;
            float b1 = u0v * u0v + u1v * u1v;
            #pragma unroll
            for (int off = 2; off <= 16; off <<= 1) {
                b0 += __shfl_xor_sync(0xffffffffu, b0, off);
                b1 += __shfl_xor_sync(0xffffffffu, b1, off);
            }
            if (lane == 0) { sBR[wid][0] = b0; sBR[wid][1] = b1; }
        }
        __syncthreads();   // sGW + sBR visible

        float lu0 = 0.f, lu1 = 0.f;
        if (mh == 0) {
            #pragma unroll
            for (int w = 0; w < 4; ++w) { lu0 += sBR[w][0]; lu1 += sBR[w][1]; }
            if (tid == 0) {
                uint32_t ra = peer_addr(smem_u32(&eU[0]), peer);
                st_peer_f32(ra, lu0); st_peer_f32(ra + 4, lu1);
            }
        } else {
            // group B: memory update (overlaps group A's out-LN exchange)
            const float gw = sGW;
            float nmA[K_], nmB[K_];
            #pragma unroll
            for (int j = 0; j < K_; ++j) {
                const float er0 = sigmf(ae0[j] + ce0 + egbv.x);
                const float er1 = sigmf(ae1[j] + ce1 + egbv.y);
                const float wr0 = (g0[j] - sMean[j]) * sRstd[j] * wclngv.x + wclnbv.x;
                const float wr1 = (g1[j] - sMean[j]) * sRstd[j] * wclngv.y + wclnbv.y;
                const float al = gw * sEvict[j];
                nmA[j] = sM[og][j]     * (1.f - al * er0) + al * wr0;
                nmB[j] = sM[og + 1][j] * (1.f - al * er1) + al * wr1;
            }
            if (ih == 0) {
                float4* rA = reinterpret_cast<float4*>(sM[og]);
                float4* rB = reinterpret_cast<float4*>(sM[og + 1]);
                rA[0] = make_float4(nmA[0], nmA[1], nmA[2], nmA[3]);
                rA[1] = make_float4(nmA[4], nmA[5], nmA[6], nmA[7]);
                rA[2] = make_float4(nmA[8], nmA[9], nmA[10], nmA[11]);
                rA[3] = make_float4(nmA[12], nmA[13], nmA[14], nmA[15]);
                rB[0] = make_float4(nmB[0], nmB[1], nmB[2], nmB[3]);
                rB[1] = make_float4(nmB[4], nmB[5], nmB[6], nmB[7]);
                rB[2] = make_float4(nmB[8], nmB[9], nmB[10], nmB[11]);
                rB[3] = make_float4(nmB[12], nmB[13], nmB[14], nmB[15]);
            } else {
                uint32_t ra = peer_addr(smem_u32(&sM[og][0]), peer);
                st_peer_f128(ra,      make_float4(nmA[0], nmA[1], nmA[2], nmA[3]));
                st_peer_f128(ra + 16, make_float4(nmA[4], nmA[5], nmA[6], nmA[7]));
                st_peer_f128(ra + 32, make_float4(nmA[8], nmA[9], nmA[10], nmA[11]));
                st_peer_f128(ra + 48, make_float4(nmA[12], nmA[13], nmA[14], nmA[15]));
                uint32_t rb = peer_addr(smem_u32(&sM[og + 1][0]), peer);
                st_peer_f128(rb,      make_float4(nmB[0], nmB[1], nmB[2], nmB[3]));
                st_peer_f128(rb + 16, make_float4(nmB[4], nmB[5], nmB[6], nmB[7]));
                st_peer_f128(rb + 32, make_float4(nmB[8], nmB[9], nmB[10], nmB[11]));
                st_peer_f128(rb + 48, make_float4(nmB[12], nmB[13], nmB[14], nmB[15]));
            }
        }
        cluster_sync_();   // B4: out-LN partials + peer M halves visible

        if (mh == 0 && ih == 0) {
            const float usum = lu0 + eU[0], usq = lu1 + eU[1];
            const float um = usum * (1.f / D_);
            const float uv = usq * (1.f / D_) - um * um;
            const float rr = rsqrtf(uv + EPSLN);
            float* po = out + ((size_t)t * B_ + b) * D_ + og;
            po[0] = (u0v - um) * rr * ongv.x + onbv.x;
            po[1] = (u1v - um) * rr * ongv.y + onbv.y;
        }
    }

    __syncthreads();
    // proto = transpose(M, (1,0,2)) : [K, B, d]
    if (mh == 0 && ih == 0) {
        #pragma unroll
        for (int j = 0; j < K_; ++j) {
            out[(size_t)S_ * B_ * D_ + ((size_t)j * B_ + b) * D_ + og]     = sM[og][j];
            out[(size_t)S_ * B_ * D_ + ((size_t)j * B_ + b) * D_ + og + 1] = sM[og + 1][j];
        }
    }
}

extern "C" void kernel_launch(void* const* d_in, const int* in_sizes, int n_in,
                              void* d_out, int out_size) {
    (void)in_sizes; (void)n_in; (void)out_size;
    memunit_kernel<<<2 * B_, NT>>>(
        (const float*)d_in[0],  (const float*)d_in[1],
        (const float*)d_in[2],  (const float*)d_in[3],
        (const float*)d_in[4],  (const float*)d_in[5],
        (const float*)d_in[6],  (const float*)d_in[7],
        (const float*)d_in[8],  (const float*)d_in[9],
        (const float*)d_in[10], (const float*)d_in[11],
        (const float*)d_in[12], (const float*)d_in[13],
        (const float*)d_in[14], (const float*)d_in[15],
        (const float*)d_in[16], (const float*)d_in[17],
        (const float*)d_in[18], (const float*)d_in[19],
        (const float*)d_in[20], (const float*)d_in[21],
        (const float*)d_in[22], (const float*)d_in[23],
        (float*)d_out);
}